// round 7
// baseline (speedup 1.0000x reference)
#include <cuda_runtime.h>

#define LEVEL 256
#define NBLK  8
#define HH    1024
#define WW    1024
#define BM    128
#define BN    128
#define TV    640.0f       // (BM*BN)/LEVEL*THRESH

// per-block uint8 mapping tables (B=16, 64 blocks, 256 bins)
__device__ unsigned char g_maps8[16 * NBLK * NBLK * LEVEL];

// ============================================================================
// Kernel 1: per-block histogram (per-warp u32 smem atomics) + clip + CDF->map
// grid: (64, B), block: 128 threads
// ============================================================================
__global__ __launch_bounds__(128) void hist_maps_kernel(const float* __restrict__ img) {
    __shared__ unsigned int h4[4][LEVEL];   // per-warp histograms, 4 KB
    __shared__ float cs[LEVEL];
    __shared__ int   wsum[4];

    const int t    = threadIdx.x;
    const int lane = t & 31;
    const int warp = t >> 5;
    const int blk  = blockIdx.x;
    const int b    = blockIdx.y;
    const int bi   = blk >> 3, bj = blk & 7;

    #pragma unroll
    for (int k = 0; k < 8; ++k) ((unsigned int*)h4)[t + k * 128] = 0u;
    __syncthreads();

    const float* base = img + ((size_t)b * HH + (size_t)bi * BM) * WW + bj * BN;
    unsigned int* hw = h4[warp];
    #pragma unroll 8
    for (int k = 0; k < 32; ++k) {
        int idx = k * 128 + t;
        int row = idx >> 5;
        int c4  = idx & 31;
        float4 p = *reinterpret_cast<const float4*>(base + (size_t)row * WW + c4 * 4);
        atomicAdd(&hw[(int)p.x], 1u);
        atomicAdd(&hw[(int)p.y], 1u);
        atomicAdd(&hw[(int)p.z], 1u);
        atomicAdd(&hw[(int)p.w], 1u);
    }
    __syncthreads();

    float h0 = (float)(h4[0][t]       + h4[1][t]       + h4[2][t]       + h4[3][t]);
    float h1 = (float)(h4[0][t + 128] + h4[1][t + 128] + h4[2][t + 128] + h4[3][t + 128]);

    // ---- clip: redistribute excess above TV uniformly ----
    int eloc = (int)fmaxf(h0 - TV, 0.f) + (int)fmaxf(h1 - TV, 0.f);
    #pragma unroll
    for (int off = 16; off; off >>= 1)
        eloc += __shfl_xor_sync(0xffffffffu, eloc, off);
    if (lane == 0) wsum[warp] = eloc;
    __syncthreads();
    float me = (float)(wsum[0] + wsum[1] + wsum[2] + wsum[3]) * (1.0f / 256.0f);
    cs[t]       = floorf((h0 >= TV) ? (TV + me) : (h0 + me));
    cs[t + 128] = floorf((h1 >= TV) ? (TV + me) : (h1 + me));
    __syncthreads();

    // ---- inclusive scan over 256 bins (warp 0) ----
    if (warp == 0) {
        float run = 0.f;
        #pragma unroll
        for (int ch = 0; ch < 8; ++ch) {
            float v = cs[ch * 32 + lane];
            #pragma unroll
            for (int off = 1; off < 32; off <<= 1) {
                float n = __shfl_up_sync(0xffffffffu, v, off);
                if (lane >= off) v += n;
            }
            v += run;
            cs[ch * 32 + lane] = v;
            run = __shfl_sync(0xffffffffu, v, 31);
        }
    }
    __syncthreads();

    // ---- map = floor(cdf * 255/16384) & 255, packed uchar4 store ----
    if (t < 64) {
        unsigned char* gm = g_maps8 + (size_t)(b * 64 + blk) * LEVEL;
        uchar4 q;
        q.x = (unsigned char)(((int)floorf(cs[4 * t + 0] * (255.0f / 16384.0f))) & 255);
        q.y = (unsigned char)(((int)floorf(cs[4 * t + 1] * (255.0f / 16384.0f))) & 255);
        q.z = (unsigned char)(((int)floorf(cs[4 * t + 2] * (255.0f / 16384.0f))) & 255);
        q.w = (unsigned char)(((int)floorf(cs[4 * t + 3] * (255.0f / 16384.0f))) & 255);
        *reinterpret_cast<uchar4*>(gm + 4 * t) = q;
    }
}

// ============================================================================
// Kernel 2: bilinear blend via factored form o = lu + x*d1 + y*e + xy*f.
// float4 LUT {lu, d1, e, f} replicated 8x -> LDS.128 structurally conflict-free.
// All FMA steps exactly representable even on extrapolation margins (|o|<1024,
// grid 2^-14 => numerator < 2^24). EXT path handles trunc-toward-zero + %256
// for edge tiles where weights go negative; interior uses plain floorf.
// grid: (16, 16, B) tiles of 64x64; block: (16,16); float4 per thread
// ============================================================================
template <bool EXT>
__device__ __forceinline__ void apply_body(
    const float* __restrict__ ip, float* __restrict__ op,
    const float4* __restrict__ smv,
    int i0, int ty, int jbase, bool xz, int r, const float* yw)
{
    const float inv = 1.0f / 128.0f;
    #pragma unroll
    for (int k = 0; k < 4; ++k) {
        const int i = i0 + ty + k * 16;
        const float xw = xz ? 0.f : (float)(i - r * 128 - 64) * inv;
        float xy[4];
        #pragma unroll
        for (int u = 0; u < 4; ++u) xy[u] = xw * yw[u];   // exact: kj * 2^-14

        const float4 p = *reinterpret_cast<const float4*>(ip + (size_t)i * WW + jbase);
        float vals[4] = {p.x, p.y, p.z, p.w};
        float res[4];
        #pragma unroll
        for (int u = 0; u < 4; ++u) {
            const float4 m = smv[((int)vals[u]) << 3];    // conflict-free LDS.128
            const float o = fmaf(xw, m.y, fmaf(yw[u], m.z, fmaf(xy[u], m.w, m.x)));
            if (EXT)
                res[u] = (float)(((int)o) & 255);         // trunc toward 0 + %256
            else
                res[u] = floorf(o);                       // o in [0,255] here
        }
        __stcs(reinterpret_cast<float4*>(op + (size_t)i * WW + jbase),
               make_float4(res[0], res[1], res[2], res[3]));
    }
}

__global__ __launch_bounds__(256) void apply_kernel(const float* __restrict__ img,
                                                    float* __restrict__ out) {
    __shared__ float4 sm4[LEVEL * 8];   // 32 KB

    const int tx   = threadIdx.x;
    const int ty   = threadIdx.y;
    const int tid  = ty * 16 + tx;
    const int lane = tid & 31;
    const int l8   = lane & 7;
    const int i0   = blockIdx.y * 64;
    const int j0   = blockIdx.x * 64;
    const int b    = blockIdx.z;

    const int r  = (i0 < 64) ? 0 : ((i0 - 64) >> 7);
    const int c  = (j0 < 64) ? 0 : ((j0 - 64) >> 7);
    const int rp = min(r + 1, NBLK - 1);
    const int cp = min(c + 1, NBLK - 1);

    // build LUT entry for value v = tid; 8 rotated copies (conflict-free STS)
    {
        const unsigned char* gm = g_maps8 + (size_t)b * 64 * LEVEL;
        const int lu = gm[(r  * 8 + c ) * LEVEL + tid];
        const int lb = gm[(rp * 8 + c ) * LEVEL + tid];
        const int ru = gm[(r  * 8 + cp) * LEVEL + tid];
        const int rb = gm[(rp * 8 + cp) * LEVEL + tid];
        const float4 e4 = make_float4((float)lu, (float)(lb - lu),
                                      (float)(ru - lu), (float)(rb - ru - lb + lu));
        #pragma unroll
        for (int k = 0; k < 8; ++k)
            sm4[tid * 8 + ((lane + k) & 7)] = e4;
    }
    __syncthreads();

    const bool xz = (r >= NBLK - 1);
    const bool yz = (c >= NBLK - 1);

    const int jbase = j0 + tx * 4;
    float yw[4];
    #pragma unroll
    for (int u = 0; u < 4; ++u)
        yw[u] = yz ? 0.f : (float)(jbase + u - c * 128 - 64) * (1.0f / 128.0f);

    const float*  ip  = img + (size_t)b * HH * WW;
    float*        op  = out + (size_t)b * HH * WW;
    const float4* smv = sm4 + l8;

    // extrapolation (negative weights) only in the first half-block band
    if (blockIdx.x == 0 || blockIdx.y == 0)
        apply_body<true >(ip, op, smv, i0, ty, jbase, xz, r, yw);
    else
        apply_body<false>(ip, op, smv, i0, ty, jbase, xz, r, yw);
}

extern "C" void kernel_launch(void* const* d_in, const int* in_sizes, int n_in,
                              void* d_out, int out_size) {
    const float* img = (const float*)d_in[0];
    float*       out = (float*)d_out;
    const int B = in_sizes[0] / (HH * WW);   // 16
    hist_maps_kernel<<<dim3(NBLK * NBLK, B), 128>>>(img);
    apply_kernel<<<dim3(16, 16, B), dim3(16, 16)>>>(img, out);
}

// round 9
// speedup vs baseline: 1.0125x; 1.0125x over previous
#include <cuda_runtime.h>

#define LEVEL 256
#define NBLK  8
#define HH    1024
#define WW    1024
#define BM    128
#define BN    128
#define TV    640.0f       // (BM*BN)/LEVEL*THRESH

// per-block uint8 mapping tables (B=16, 64 blocks, 256 bins)
__device__ unsigned char g_maps8[16 * NBLK * NBLK * LEVEL];

// ============================================================================
// Kernel 1: per-block histogram (per-warp u32 smem atomics) + clip + CDF->map
// grid: (64, B), block: 128 threads
// ============================================================================
__global__ __launch_bounds__(128) void hist_maps_kernel(const float* __restrict__ img) {
    __shared__ unsigned int h4[4][LEVEL];   // per-warp histograms, 4 KB
    __shared__ float cs[LEVEL];
    __shared__ int   wsum[4];

    const int t    = threadIdx.x;
    const int lane = t & 31;
    const int warp = t >> 5;
    const int blk  = blockIdx.x;
    const int b    = blockIdx.y;
    const int bi   = blk >> 3, bj = blk & 7;

    #pragma unroll
    for (int k = 0; k < 8; ++k) ((unsigned int*)h4)[t + k * 128] = 0u;
    __syncthreads();

    const float* base = img + ((size_t)b * HH + (size_t)bi * BM) * WW + bj * BN;
    unsigned int* hw = h4[warp];
    #pragma unroll 8
    for (int k = 0; k < 32; ++k) {
        int idx = k * 128 + t;
        int row = idx >> 5;
        int c4  = idx & 31;
        float4 p = *reinterpret_cast<const float4*>(base + (size_t)row * WW + c4 * 4);
        atomicAdd(&hw[(int)p.x], 1u);
        atomicAdd(&hw[(int)p.y], 1u);
        atomicAdd(&hw[(int)p.z], 1u);
        atomicAdd(&hw[(int)p.w], 1u);
    }
    __syncthreads();

    float h0 = (float)(h4[0][t]       + h4[1][t]       + h4[2][t]       + h4[3][t]);
    float h1 = (float)(h4[0][t + 128] + h4[1][t + 128] + h4[2][t + 128] + h4[3][t + 128]);

    // ---- clip: redistribute excess above TV uniformly ----
    int eloc = (int)fmaxf(h0 - TV, 0.f) + (int)fmaxf(h1 - TV, 0.f);
    #pragma unroll
    for (int off = 16; off; off >>= 1)
        eloc += __shfl_xor_sync(0xffffffffu, eloc, off);
    if (lane == 0) wsum[warp] = eloc;
    __syncthreads();
    float me = (float)(wsum[0] + wsum[1] + wsum[2] + wsum[3]) * (1.0f / 256.0f);
    cs[t]       = floorf((h0 >= TV) ? (TV + me) : (h0 + me));
    cs[t + 128] = floorf((h1 >= TV) ? (TV + me) : (h1 + me));
    __syncthreads();

    // ---- inclusive scan over 256 bins (warp 0) ----
    if (warp == 0) {
        float run = 0.f;
        #pragma unroll
        for (int ch = 0; ch < 8; ++ch) {
            float v = cs[ch * 32 + lane];
            #pragma unroll
            for (int off = 1; off < 32; off <<= 1) {
                float n = __shfl_up_sync(0xffffffffu, v, off);
                if (lane >= off) v += n;
            }
            v += run;
            cs[ch * 32 + lane] = v;
            run = __shfl_sync(0xffffffffu, v, 31);
        }
    }
    __syncthreads();

    // ---- map = floor(cdf * 255/16384) & 255, packed uchar4 store ----
    if (t < 64) {
        unsigned char* gm = g_maps8 + (size_t)(b * 64 + blk) * LEVEL;
        uchar4 q;
        q.x = (unsigned char)(((int)floorf(cs[4 * t + 0] * (255.0f / 16384.0f))) & 255);
        q.y = (unsigned char)(((int)floorf(cs[4 * t + 1] * (255.0f / 16384.0f))) & 255);
        q.z = (unsigned char)(((int)floorf(cs[4 * t + 2] * (255.0f / 16384.0f))) & 255);
        q.w = (unsigned char)(((int)floorf(cs[4 * t + 3] * (255.0f / 16384.0f))) & 255);
        *reinterpret_cast<uchar4*>(gm + 4 * t) = q;
    }
}

// ============================================================================
// Kernel 2: bilinear blend. Packed u32 map {lu,lb,ru,rb}, replicated 32x
// (bank == lane) -> LDS.32 structurally conflict-free (1 wavefront/warp-op).
// PRMT magic unpack: byte -> float(32768 + byte), bias cancels in diffs and
// is removed once before the last FMA. All steps exactly representable
// (multiples of 2^-14, |.| < 2^10+2^15 within one binade) -> bit-exact.
// Interior tiles: o in [0,255] -> single FRND epilogue. Edge tiles
// (blockIdx.x==0 || blockIdx.y==0, negative weights): trunc + %256.
// grid: (16, 16, B) tiles of 64x64; block: (16,16); float4 per thread
// ============================================================================
template <bool EXT>
__device__ __forceinline__ void apply_body(
    const float* __restrict__ ip, float* __restrict__ op,
    const unsigned int* __restrict__ sml,
    int i0, int ty, int jbase, bool xz, int r, const float* yw)
{
    const float inv = 1.0f / 128.0f;
    #pragma unroll
    for (int k = 0; k < 4; ++k) {
        const int i = i0 + ty + k * 16;
        const float xw = xz ? 0.f : (float)(i - r * 128 - 64) * inv;
        const float4 p = *reinterpret_cast<const float4*>(ip + (size_t)i * WW + jbase);
        float vals[4] = {p.x, p.y, p.z, p.w};
        float res[4];
        #pragma unroll
        for (int u = 0; u < 4; ++u) {
            const unsigned int m = sml[((int)vals[u]) * 32];   // conflict-free LDS.32
            // magic floats: value = 32768 + byte (exact; ulp <= 2^-8 in binade)
            const float lu = __uint_as_float(__byte_perm(m, 0x47000000u, 0x7404));
            const float lb = __uint_as_float(__byte_perm(m, 0x47000000u, 0x7414));
            const float ru = __uint_as_float(__byte_perm(m, 0x47000000u, 0x7424));
            const float rb = __uint_as_float(__byte_perm(m, 0x47000000u, 0x7434));
            const float d1 = lb - lu;                 // exact int diff (bias cancels)
            const float d2 = rb - ru;
            const float a  = fmaf(xw, d1, lu);        // 32768 + a_true, exact
            const float bb = fmaf(xw, d2, ru);        // 32768 + b_true, exact
            const float d3 = bb - a;                  // exact
            const float o  = fmaf(yw[u], d3, a - 32768.0f);   // exact bilinear value
            if (EXT)
                res[u] = (float)(((int)o) & 255);     // trunc toward 0 + %256
            else
                res[u] = floorf(o);                   // o in [0,255] here
        }
        __stcs(reinterpret_cast<float4*>(op + (size_t)i * WW + jbase),
               make_float4(res[0], res[1], res[2], res[3]));
    }
}

__global__ __launch_bounds__(256) void apply_kernel(const float* __restrict__ img,
                                                    float* __restrict__ out) {
    __shared__ unsigned int sm[LEVEL * 32];   // 32 KB

    const int tx   = threadIdx.x;
    const int ty   = threadIdx.y;
    const int tid  = ty * 16 + tx;
    const int lane = tid & 31;
    const int i0   = blockIdx.y * 64;
    const int j0   = blockIdx.x * 64;
    const int b    = blockIdx.z;

    const int r  = (i0 < 64) ? 0 : ((i0 - 64) >> 7);
    const int c  = (j0 < 64) ? 0 : ((j0 - 64) >> 7);
    const int rp = min(r + 1, NBLK - 1);
    const int cp = min(c + 1, NBLK - 1);

    // packed word {lu, lb, ru, rb} for value v = tid, replicated to all banks
    {
        const unsigned char* gm = g_maps8 + (size_t)b * 64 * LEVEL;
        unsigned int w = (unsigned int)gm[(r  * 8 + c ) * LEVEL + tid]
                       | ((unsigned int)gm[(rp * 8 + c ) * LEVEL + tid] << 8)
                       | ((unsigned int)gm[(r  * 8 + cp) * LEVEL + tid] << 16)
                       | ((unsigned int)gm[(rp * 8 + cp) * LEVEL + tid] << 24);
        #pragma unroll
        for (int k = 0; k < 32; ++k)
            sm[tid * 32 + ((lane + k) & 31)] = w;     // rotated: conflict-free fill
    }
    __syncthreads();

    const bool xz = (r >= NBLK - 1);
    const bool yz = (c >= NBLK - 1);

    const int jbase = j0 + tx * 4;
    float yw[4];
    #pragma unroll
    for (int u = 0; u < 4; ++u)
        yw[u] = yz ? 0.f : (float)(jbase + u - c * 128 - 64) * (1.0f / 128.0f);

    const float*        ip  = img + (size_t)b * HH * WW;
    float*              op  = out + (size_t)b * HH * WW;
    const unsigned int* sml = sm + lane;

    // extrapolation (negative weights) only in the first half-block band
    if (blockIdx.x == 0 || blockIdx.y == 0)
        apply_body<true >(ip, op, sml, i0, ty, jbase, xz, r, yw);
    else
        apply_body<false>(ip, op, sml, i0, ty, jbase, xz, r, yw);
}

extern "C" void kernel_launch(void* const* d_in, const int* in_sizes, int n_in,
                              void* d_out, int out_size) {
    const float* img = (const float*)d_in[0];
    float*       out = (float*)d_out;
    const int B = in_sizes[0] / (HH * WW);   // 16
    hist_maps_kernel<<<dim3(NBLK * NBLK, B), 128>>>(img);
    apply_kernel<<<dim3(16, 16, B), dim3(16, 16)>>>(img, out);
}

// round 10
// speedup vs baseline: 1.0511x; 1.0381x over previous
#include <cuda_runtime.h>

#define LEVEL 256
#define NBLK  8
#define HH    1024
#define WW    1024
#define TV    640.0f       // (128*128)/LEVEL*THRESH

// per-block uint8 mapping tables (B=16, 64 blocks, 256 bins)
__device__ unsigned char g_maps8[16 * 64 * LEVEL];
// per-image completion counters (hist CTAs done)
__device__ unsigned int  g_done[16];

__global__ void reset_kernel() {
    if (threadIdx.x < 16) g_done[threadIdx.x] = 0u;
}

// ============================================================================
// Fused kernel. bid < 1024: hist role (64 CTAs per image, image-major so
// image 0 completes first). bid >= 1024: apply role; spins on g_done[b]==64.
// 256 threads everywhere; 33KB shared union -> 6 CTAs/SM -> wave 1 (888 CTAs)
// is hist-only; in-order dispatch makes the producer->consumer spin safe.
// ============================================================================
__global__ __launch_bounds__(256) void fused_kernel(const float* __restrict__ img,
                                                    float* __restrict__ out) {
    __shared__ union {
        struct { unsigned int h8[8][LEVEL]; float cs[LEVEL]; int wsum[8]; } h; // 9KB
        struct { unsigned int tbl[LEVEL * 32]; } a;                            // 32KB
    } u;

    const int bid = blockIdx.x;
    const int t   = threadIdx.x;

    if (bid < 1024) {
        // ==================== HIST role ====================
        const int b    = bid >> 6;
        const int blk  = bid & 63;
        const int bi   = blk >> 3, bj = blk & 7;
        const int lane = t & 31, warp = t >> 5;   // 8 warps

        #pragma unroll
        for (int k = 0; k < 8; ++k) ((unsigned int*)u.h.h8)[t + k * 256] = 0u;
        __syncthreads();

        // accumulate 128x128 region: per-warp u32 smem-atomic histograms
        const float* base = img + ((size_t)b * HH + (size_t)bi * 128) * WW + bj * 128;
        unsigned int* hw = u.h.h8[warp];
        #pragma unroll 8
        for (int k = 0; k < 16; ++k) {
            int idx = k * 256 + t;          // 0..4095 vec index
            int row = idx >> 5;
            int c4  = idx & 31;
            float4 p = *reinterpret_cast<const float4*>(base + (size_t)row * WW + c4 * 4);
            atomicAdd(&hw[(int)p.x], 1u);
            atomicAdd(&hw[(int)p.y], 1u);
            atomicAdd(&hw[(int)p.z], 1u);
            atomicAdd(&hw[(int)p.w], 1u);
        }
        __syncthreads();

        // merge 8 sub-hists; thread t owns bin t
        unsigned int s = 0u;
        #pragma unroll
        for (int w = 0; w < 8; ++w) s += u.h.h8[w][t];
        const float h = (float)s;

        // clip: redistribute excess above TV uniformly
        int eloc = (int)fmaxf(h - TV, 0.f);
        #pragma unroll
        for (int off = 16; off; off >>= 1)
            eloc += __shfl_xor_sync(0xffffffffu, eloc, off);
        if (lane == 0) u.h.wsum[warp] = eloc;
        __syncthreads();
        int tot = 0;
        #pragma unroll
        for (int w = 0; w < 8; ++w) tot += u.h.wsum[w];
        const float me = (float)tot * (1.0f / 256.0f);
        u.h.cs[t] = floorf((h >= TV) ? (TV + me) : (h + me));
        __syncthreads();

        // inclusive scan over 256 bins (warp 0)
        if (warp == 0) {
            float run = 0.f;
            #pragma unroll
            for (int ch = 0; ch < 8; ++ch) {
                float v = u.h.cs[ch * 32 + lane];
                #pragma unroll
                for (int off = 1; off < 32; off <<= 1) {
                    float n = __shfl_up_sync(0xffffffffu, v, off);
                    if (lane >= off) v += n;
                }
                v += run;
                u.h.cs[ch * 32 + lane] = v;
                run = __shfl_sync(0xffffffffu, v, 31);
            }
        }
        __syncthreads();

        // map = floor(cdf * 255/16384) & 255, packed uchar4 store
        if (t < 64) {
            unsigned char* gm = g_maps8 + (size_t)(b * 64 + blk) * LEVEL;
            uchar4 q;
            q.x = (unsigned char)(((int)floorf(u.h.cs[4 * t + 0] * (255.0f / 16384.0f))) & 255);
            q.y = (unsigned char)(((int)floorf(u.h.cs[4 * t + 1] * (255.0f / 16384.0f))) & 255);
            q.z = (unsigned char)(((int)floorf(u.h.cs[4 * t + 2] * (255.0f / 16384.0f))) & 255);
            q.w = (unsigned char)(((int)floorf(u.h.cs[4 * t + 3] * (255.0f / 16384.0f))) & 255);
            *reinterpret_cast<uchar4*>(gm + 4 * t) = q;
        }
        __threadfence();          // release: map stores visible before flag
        __syncthreads();
        if (t == 0) atomicAdd(&g_done[b], 1u);

    } else {
        // ==================== APPLY role ====================
        const int a    = bid - 1024;
        const int b    = a >> 8;
        const int tile = a & 255;
        const int i0   = (tile >> 4) * 64;
        const int j0   = (tile & 15) * 64;
        const int tx   = t & 15, ty = t >> 4;
        const int lane = t & 31;

        // wait for this image's 64 hist CTAs (volatile load spin, cheap in L2)
        if (t == 0) {
            volatile unsigned int* f = &g_done[b];
            while (*f < 64u) __nanosleep(256);
        }
        __syncthreads();          // acquire for whole CTA

        const int r  = (i0 < 64) ? 0 : ((i0 - 64) >> 7);
        const int c  = (j0 < 64) ? 0 : ((j0 - 64) >> 7);
        const int rp = min(r + 1, NBLK - 1);
        const int cp = min(c + 1, NBLK - 1);

        // packed word {lu, lb, ru, rb} for value v = t, replicated to all banks
        {
            const unsigned char* gm = g_maps8 + (size_t)b * 64 * LEVEL;
            unsigned int w = (unsigned int)gm[(r  * 8 + c ) * LEVEL + t]
                           | ((unsigned int)gm[(rp * 8 + c ) * LEVEL + t] << 8)
                           | ((unsigned int)gm[(r  * 8 + cp) * LEVEL + t] << 16)
                           | ((unsigned int)gm[(rp * 8 + cp) * LEVEL + t] << 24);
            #pragma unroll
            for (int k = 0; k < 32; ++k)
                u.a.tbl[t * 32 + ((lane + k) & 31)] = w;   // rotated conflict-free fill
        }
        __syncthreads();

        const bool xz = (r >= NBLK - 1);
        const bool yz = (c >= NBLK - 1);
        const bool ext = (i0 == 0) || (j0 == 0);   // extrapolation band (neg weights)

        const int jbase = j0 + tx * 4;
        float yw[4];
        #pragma unroll
        for (int uu = 0; uu < 4; ++uu)
            yw[uu] = yz ? 0.f : (float)(jbase + uu - c * 128 - 64) * (1.0f / 128.0f);

        const float*        ip  = img + (size_t)b * HH * WW;
        float*              op  = out + (size_t)b * HH * WW;
        const unsigned int* sml = u.a.tbl + lane;

        #pragma unroll
        for (int k = 0; k < 4; ++k) {
            const int i = i0 + ty + k * 16;
            const float xw = xz ? 0.f : (float)(i - r * 128 - 64) * (1.0f / 128.0f);
            const float4 p = *reinterpret_cast<const float4*>(ip + (size_t)i * WW + jbase);
            float vals[4] = {p.x, p.y, p.z, p.w};
            float res[4];
            #pragma unroll
            for (int uu = 0; uu < 4; ++uu) {
                const unsigned int m = sml[((int)vals[uu]) * 32];   // conflict-free LDS.32
                // magic floats: value = 32768 + byte (exact)
                const float lu = __uint_as_float(__byte_perm(m, 0x47000000u, 0x7404));
                const float lb = __uint_as_float(__byte_perm(m, 0x47000000u, 0x7414));
                const float ru = __uint_as_float(__byte_perm(m, 0x47000000u, 0x7424));
                const float rb = __uint_as_float(__byte_perm(m, 0x47000000u, 0x7434));
                const float d1 = lb - lu;               // exact (bias cancels)
                const float d2 = rb - ru;
                const float aa = fmaf(xw, d1, lu);      // 32768 + a_true, exact
                const float bb = fmaf(xw, d2, ru);
                const float d3 = bb - aa;               // exact
                const float o  = fmaf(yw[uu], d3, aa - 32768.0f);  // exact bilinear
                res[uu] = ext ? (float)(((int)o) & 255)  // trunc toward 0 + %256
                              : floorf(o);               // o in [0,255] interior
            }
            __stcs(reinterpret_cast<float4*>(op + (size_t)i * WW + jbase),
                   make_float4(res[0], res[1], res[2], res[3]));
        }
    }
}

extern "C" void kernel_launch(void* const* d_in, const int* in_sizes, int n_in,
                              void* d_out, int out_size) {
    const float* img = (const float*)d_in[0];
    float*       out = (float*)d_out;
    reset_kernel<<<1, 32>>>();
    fused_kernel<<<1024 + 4096, 256>>>(img, out);
}

// round 11
// speedup vs baseline: 1.1741x; 1.1170x over previous
#include <cuda_runtime.h>

#define LEVEL 256
#define NBLK  8
#define HH    1024
#define WW    1024
#define TV    640.0f       // (128*128)/LEVEL*THRESH

// per-block uint8 mapping tables (B=16, 64 blocks, 256 bins)
__device__ unsigned char g_maps8[16 * 64 * LEVEL];
// per-image producer counters + consumer counters (self-resetting each launch)
__device__ unsigned int  g_done[16];
__device__ unsigned int  g_cons[16];

// ============================================================================
// Fused kernel. bid < 1024: hist role (64 CTAs per image, image-major).
// bid >= 1024: apply role; spins on g_done[b]==64, then self-resets flags
// once all 256 apply CTAs of the image have passed (net-zero state/launch).
// 256 threads; 16KB shared union + <=32 regs -> 8 CTAs/SM (64 warps).
// ============================================================================
__global__ __launch_bounds__(256, 8) void fused_kernel(const float* __restrict__ img,
                                                       float* __restrict__ out) {
    __shared__ union {
        struct { unsigned int h8[8][LEVEL]; float cs[LEVEL]; int wsum[8]; } h; // ~9KB
        unsigned int tbl[LEVEL * 16];                                          // 16KB
    } u;

    const int bid = blockIdx.x;
    const int t   = threadIdx.x;

    if (bid < 1024) {
        // ==================== HIST role ====================
        const int b    = bid >> 6;
        const int blk  = bid & 63;
        const int bi   = blk >> 3, bj = blk & 7;
        const int lane = t & 31, warp = t >> 5;   // 8 warps

        #pragma unroll
        for (int k = 0; k < 8; ++k) ((unsigned int*)u.h.h8)[t + k * 256] = 0u;
        __syncthreads();

        const float* base = img + ((size_t)b * HH + (size_t)bi * 128) * WW + bj * 128;
        unsigned int* hw = u.h.h8[warp];
        #pragma unroll 8
        for (int k = 0; k < 16; ++k) {
            int idx = k * 256 + t;
            int row = idx >> 5;
            int c4  = idx & 31;
            float4 p = *reinterpret_cast<const float4*>(base + (size_t)row * WW + c4 * 4);
            atomicAdd(&hw[(int)p.x], 1u);
            atomicAdd(&hw[(int)p.y], 1u);
            atomicAdd(&hw[(int)p.z], 1u);
            atomicAdd(&hw[(int)p.w], 1u);
        }
        __syncthreads();

        unsigned int s = 0u;
        #pragma unroll
        for (int w = 0; w < 8; ++w) s += u.h.h8[w][t];
        const float h = (float)s;

        // clip: redistribute excess above TV uniformly
        int eloc = (int)fmaxf(h - TV, 0.f);
        #pragma unroll
        for (int off = 16; off; off >>= 1)
            eloc += __shfl_xor_sync(0xffffffffu, eloc, off);
        if (lane == 0) u.h.wsum[warp] = eloc;
        __syncthreads();
        int tot = 0;
        #pragma unroll
        for (int w = 0; w < 8; ++w) tot += u.h.wsum[w];
        const float me = (float)tot * (1.0f / 256.0f);
        u.h.cs[t] = floorf((h >= TV) ? (TV + me) : (h + me));
        __syncthreads();

        // inclusive scan over 256 bins (warp 0)
        if (warp == 0) {
            float run = 0.f;
            #pragma unroll
            for (int ch = 0; ch < 8; ++ch) {
                float v = u.h.cs[ch * 32 + lane];
                #pragma unroll
                for (int off = 1; off < 32; off <<= 1) {
                    float n = __shfl_up_sync(0xffffffffu, v, off);
                    if (lane >= off) v += n;
                }
                v += run;
                u.h.cs[ch * 32 + lane] = v;
                run = __shfl_sync(0xffffffffu, v, 31);
            }
        }
        __syncthreads();

        if (t < 64) {
            unsigned char* gm = g_maps8 + (size_t)(b * 64 + blk) * LEVEL;
            uchar4 q;
            q.x = (unsigned char)(((int)floorf(u.h.cs[4 * t + 0] * (255.0f / 16384.0f))) & 255);
            q.y = (unsigned char)(((int)floorf(u.h.cs[4 * t + 1] * (255.0f / 16384.0f))) & 255);
            q.z = (unsigned char)(((int)floorf(u.h.cs[4 * t + 2] * (255.0f / 16384.0f))) & 255);
            q.w = (unsigned char)(((int)floorf(u.h.cs[4 * t + 3] * (255.0f / 16384.0f))) & 255);
            *reinterpret_cast<uchar4*>(gm + 4 * t) = q;
        }
        __threadfence();          // release maps before flag
        __syncthreads();
        if (t == 0) atomicAdd(&g_done[b], 1u);

    } else {
        // ==================== APPLY role ====================
        const int a    = bid - 1024;
        const int b    = a >> 8;
        const int tile = a & 255;
        const int i0   = (tile >> 4) * 64;
        const int j0   = (tile & 15) * 64;
        const int tx   = t & 15, ty = t >> 4;
        const int lane = t & 31;

        // wait for this image's 64 hist CTAs
        if (t == 0) {
            volatile unsigned int* f = &g_done[b];
            while (*f < 64u) __nanosleep(256);
        }
        __syncthreads();          // acquire for whole CTA

        // self-reset: 256th apply CTA of image b zeroes both flags
        if (t == 0) {
            unsigned int old = atomicAdd(&g_cons[b], 1u);
            if (old == 255u) { g_done[b] = 0u; g_cons[b] = 0u; }
        }

        const int r  = (i0 < 64) ? 0 : ((i0 - 64) >> 7);
        const int c  = (j0 < 64) ? 0 : ((j0 - 64) >> 7);
        const int rp = min(r + 1, NBLK - 1);
        const int cp = min(c + 1, NBLK - 1);

        // packed word {lu, lb, ru, rb} for value v = t, 16 rotated copies
        {
            const unsigned char* gm = g_maps8 + (size_t)b * 64 * LEVEL;
            unsigned int w = (unsigned int)gm[(r  * 8 + c ) * LEVEL + t]
                           | ((unsigned int)gm[(rp * 8 + c ) * LEVEL + t] << 8)
                           | ((unsigned int)gm[(r  * 8 + cp) * LEVEL + t] << 16)
                           | ((unsigned int)gm[(rp * 8 + cp) * LEVEL + t] << 24);
            #pragma unroll
            for (int k = 0; k < 16; ++k)
                u.tbl[t * 16 + ((lane + k) & 15)] = w;
        }
        __syncthreads();

        const bool xz  = (r >= NBLK - 1);
        const bool yz  = (c >= NBLK - 1);
        const bool ext = (i0 == 0) || (j0 == 0);   // extrapolation band

        const int jbase = j0 + tx * 4;
        float yw[4];
        #pragma unroll
        for (int uu = 0; uu < 4; ++uu)
            yw[uu] = yz ? 0.f : (float)(jbase + uu - c * 128 - 64) * (1.0f / 128.0f);

        const float*        ip  = img + (size_t)b * HH * WW;
        float*              op  = out + (size_t)b * HH * WW;
        const unsigned int* sml = u.tbl + (lane & 15);

        #pragma unroll
        for (int k = 0; k < 4; ++k) {
            const int i = i0 + ty + k * 16;
            const float xw = xz ? 0.f : (float)(i - r * 128 - 64) * (1.0f / 128.0f);
            const float4 p = *reinterpret_cast<const float4*>(ip + (size_t)i * WW + jbase);
            float vals[4] = {p.x, p.y, p.z, p.w};
            float res[4];
            #pragma unroll
            for (int uu = 0; uu < 4; ++uu) {
                const unsigned int m = sml[((int)vals[uu]) * 16];  // <=2-way LDS
                // magic floats: value = 32768 + byte (exact)
                const float lu = __uint_as_float(__byte_perm(m, 0x47000000u, 0x7404));
                const float lb = __uint_as_float(__byte_perm(m, 0x47000000u, 0x7414));
                const float ru = __uint_as_float(__byte_perm(m, 0x47000000u, 0x7424));
                const float rb = __uint_as_float(__byte_perm(m, 0x47000000u, 0x7434));
                const float d1 = lb - lu;               // exact (bias cancels)
                const float d2 = rb - ru;
                const float aa = fmaf(xw, d1, lu);      // 32768 + a_true, exact
                const float bb = fmaf(xw, d2, ru);
                const float d3 = bb - aa;               // exact
                const float o  = fmaf(yw[uu], d3, aa - 32768.0f);  // exact bilinear
                res[uu] = ext ? (float)(((int)o) & 255)  // trunc toward 0 + %256
                              : floorf(o);               // o in [0,255] interior
            }
            __stcs(reinterpret_cast<float4*>(op + (size_t)i * WW + jbase),
                   make_float4(res[0], res[1], res[2], res[3]));
        }
    }
}

extern "C" void kernel_launch(void* const* d_in, const int* in_sizes, int n_in,
                              void* d_out, int out_size) {
    const float* img = (const float*)d_in[0];
    float*       out = (float*)d_out;
    fused_kernel<<<1024 + 4096, 256>>>(img, out);
}